// round 17
// baseline (speedup 1.0000x reference)
#include <cuda_runtime.h>
#include <cuda_fp16.h>
#include <stdint.h>
#include <math.h>

// ---------------------------------------------------------------------------
// DiT block. Round 17: hgemm 4-stage cp.async ring (3 tiles of lookahead).
// Rest unchanged from R16.
//   B=2, N=2048, C=1024, H=16, D=64, F=4096, M=B*N=4096
// ---------------------------------------------------------------------------

#define Mrows 4096
#define Cdim  1024
#define Fdim  4096
#define Bb    2
#define Hh    16
#define Dd    64
#define Nn_   2048

// byte offsets into scratch
#define OFF_H   ((size_t)0)
#define OFF_Q   ((size_t)8388608)
#define OFF_K   ((size_t)16777216)
#define OFF_V   ((size_t)25165824)
#define OFF_ATT ((size_t)33554432)
#define OFF_MLP ((size_t)41943040)
#define OFF_X2  ((size_t)75497472)
#define OFF_WQ  ((size_t)92274688)
#define OFF_WK  ((size_t)94371840)
#define OFF_WV  ((size_t)96468992)
#define OFF_WO  ((size_t)98566144)
#define OFF_W1  ((size_t)100663296)
#define OFF_W2  ((size_t)109051904)
__device__ __align__(1024) unsigned char g_scratch[117440512];

__device__ __forceinline__ uint32_t h2u(__half2 h) {
    return *reinterpret_cast<uint32_t*>(&h);
}

#define MMA_F16(d, a, b)                                                      \
    asm volatile(                                                             \
        "mma.sync.aligned.m16n8k16.row.col.f32.f16.f16.f32 "                  \
        "{%0,%1,%2,%3}, {%4,%5,%6,%7}, {%8,%9}, {%0,%1,%2,%3};"               \
        : "+f"(d[0]), "+f"(d[1]), "+f"(d[2]), "+f"(d[3])                      \
        : "r"(a[0]), "r"(a[1]), "r"(a[2]), "r"(a[3]), "r"(b[0]), "r"(b[1]))

#define CP_ASYNC16(dst_u32, src_ptr)                                          \
    asm volatile("cp.async.cg.shared.global [%0], [%1], 16;"                  \
                 :: "r"(dst_u32), "l"(src_ptr))
#define CP_COMMIT()  asm volatile("cp.async.commit_group;")
#define CP_WAIT(n)   asm volatile("cp.async.wait_group %0;" :: "n"(n))

#define EX2_F16X2(out_u32, in_u32)                                            \
    asm("ex2.approx.f16x2 %0, %1;" : "=r"(out_u32) : "r"(in_u32))

#define LDSM_X4(r0, r1, r2, r3, addr)                                         \
    asm volatile("ldmatrix.sync.aligned.m8n8.x4.shared.b16 "                  \
                 "{%0,%1,%2,%3}, [%4];"                                       \
                 : "=r"(r0), "=r"(r1), "=r"(r2), "=r"(r3) : "r"(addr))

#define LDSM_X4_T(r0, r1, r2, r3, addr)                                       \
    asm volatile("ldmatrix.sync.aligned.m8n8.x4.trans.shared.b16 "            \
                 "{%0,%1,%2,%3}, [%4];"                                       \
                 : "=r"(r0), "=r"(r1), "=r"(r2), "=r"(r3) : "r"(addr))

// ---------------------------------------------------------------------------
// Weight conversion fp32 -> fp16 (RN), flat balanced grid-stride.
// ---------------------------------------------------------------------------
struct ConvSet {
    const float4* in[6];
    __half2*      out[6];
    int           start[7];
};

__global__ void __launch_bounds__(256) conv_half_kernel(ConvSet cs)
{
    const int total = cs.start[6];
    const int stride = gridDim.x * 256;
    for (int i = blockIdx.x * 256 + threadIdx.x; i < total; i += stride) {
        int z = 0;
        #pragma unroll
        for (int j = 1; j < 6; j++) z = (i >= cs.start[j]) ? j : z;
        const int li = i - cs.start[z];
        const float4 v = cs.in[z][li];
        __half2 h01 = __floats2half2_rn(v.x, v.y);
        __half2 h23 = __floats2half2_rn(v.z, v.w);
        uint2 u; u.x = h2u(h01); u.y = h2u(h23);
        *(uint2*)&cs.out[z][2 * li] = u;
    }
}

// ---------------------------------------------------------------------------
// LayerNorm: one block (256 thr) per row of 1024. fp32 in, fp16 out.
// ---------------------------------------------------------------------------
__global__ void __launch_bounds__(256) ln_kernel(
    const float* __restrict__ x, const float* __restrict__ g,
    const float* __restrict__ b, __half* __restrict__ out)
{
    __shared__ float red[16];
    const int row = blockIdx.x;
    const int t = threadIdx.x;
    const float4 xv = ((const float4*)(x + (size_t)row * Cdim))[t];
    float s  = xv.x + xv.y + xv.z + xv.w;
    float ss = xv.x*xv.x + xv.y*xv.y + xv.z*xv.z + xv.w*xv.w;
    #pragma unroll
    for (int o = 16; o > 0; o >>= 1) {
        s  += __shfl_xor_sync(0xffffffffu, s,  o);
        ss += __shfl_xor_sync(0xffffffffu, ss, o);
    }
    const int w = t >> 5;
    if ((t & 31) == 0) { red[w] = s; red[8 + w] = ss; }
    __syncthreads();
    float ts = 0.f, tss = 0.f;
    #pragma unroll
    for (int i = 0; i < 8; i++) { ts += red[i]; tss += red[8 + i]; }
    const float mean = ts * (1.0f / Cdim);
    const float var  = tss * (1.0f / Cdim) - mean * mean;
    const float inv  = rsqrtf(var + 1e-6f);
    const float4 gv = ((const float4*)g)[t];
    const float4 bv = ((const float4*)b)[t];
    __half2 h01 = __floats2half2_rn((xv.x - mean) * inv * gv.x + bv.x,
                                    (xv.y - mean) * inv * gv.y + bv.y);
    __half2 h23 = __floats2half2_rn((xv.z - mean) * inv * gv.z + bv.z,
                                    (xv.w - mean) * inv * gv.w + bv.w);
    uint2 u; u.x = h2u(h01); u.y = h2u(h23);
    *(uint2*)(out + (size_t)row * Cdim + 4 * t) = u;
}

// ---------------------------------------------------------------------------
// fp16 GEMM: 4-stage cp.async ring, 128x128 CTA tile, BK=32, 4 warps (2Mx2N),
// warp tile 64x64, ldmatrix fragments.
// ---------------------------------------------------------------------------
#define GSH 40
#define TBUFH (128 * GSH)
#define NSTG 4
#define BOFFH (NSTG * TBUFH)
#define GEMM_SMEM (2 * NSTG * TBUFH * 2)

struct GemmSet {
    const __half* W[3];
    const float*  bias[3];
    void*         out[3];
};

__global__ void __launch_bounds__(128, 2) hgemm_kernel(
    const __half* __restrict__ A, GemmSet gs, const float* __restrict__ residual,
    int M, int Nc, int K, int gelu, int out_half)
{
    extern __shared__ __half smh[];
    const uint32_t sbase = (uint32_t)__cvta_generic_to_shared(smh);

    const int z = blockIdx.z;
    const __half* __restrict__ Wp  = gs.W[z];
    const float* __restrict__ bias = gs.bias[z];
    void* __restrict__ outp        = gs.out[z];

    const int tid  = threadIdx.x;
    const int wid  = tid >> 5;
    const int lane = tid & 31;
    const int lr   = lane >> 2;
    const int lc   = lane & 3;
    const int warpM = (wid & 1) * 64;
    const int warpN = (wid >> 1) * 64;
    const int bm = blockIdx.y * 128, bn = blockIdx.x * 128;

    const int a_row  = warpM + (lane & 15);
    const int a_col8 = (lane >> 4) * 8;
    const int b_row  = (lane & 7) + ((lane >> 4) & 1) * 8;
    const int b_col8 = ((lane >> 3) & 1) * 8;

    float acc[4][8][4];
    #pragma unroll
    for (int i = 0; i < 4; i++)
        #pragma unroll
        for (int j = 0; j < 8; j++)
            #pragma unroll
            for (int r = 0; r < 4; r++) acc[i][j][r] = 0.f;

    const int nk = K >> 5;

    #define LOAD_TILE(stg, k0)                                                \
    do {                                                                      \
        _Pragma("unroll")                                                     \
        for (int p = 0; p < 4; p++) {                                         \
            const int id = tid + p * 128;                                     \
            const int row = id >> 2;                                          \
            const int kc = id & 3;                                            \
            const uint32_t da = sbase + (uint32_t)(((stg) * TBUFH + row * GSH + kc * 8) * 2); \
            CP_ASYNC16(da, A + (size_t)(bm + row) * K + (k0) + kc * 8);       \
        }                                                                     \
        _Pragma("unroll")                                                     \
        for (int p = 0; p < 4; p++) {                                         \
            const int id = tid + p * 128;                                     \
            const int row = id >> 2;                                          \
            const int kc = id & 3;                                            \
            const uint32_t db = sbase + (uint32_t)((BOFFH + (stg) * TBUFH + row * GSH + kc * 8) * 2); \
            CP_ASYNC16(db, Wp + (size_t)(bn + row) * K + (k0) + kc * 8);      \
        }                                                                     \
    } while (0)

    // prologue: fill stages 0..2
    LOAD_TILE(0, 0);
    CP_COMMIT();
    if (nk > 1) { LOAD_TILE(1, 32); }
    CP_COMMIT();
    if (nk > 2) { LOAD_TILE(2, 64); }
    CP_COMMIT();

    int stg = 0;
    for (int kt = 0; kt < nk; kt++) {
        if (kt + 2 < nk)      { CP_WAIT(2); }
        else if (kt + 1 < nk) { CP_WAIT(1); }
        else                  { CP_WAIT(0); }
        __syncthreads();

        if (kt + 3 < nk) {
            const int ns = (stg + 3 >= NSTG) ? stg + 3 - NSTG : stg + 3;
            LOAD_TILE(ns, (kt + 3) << 5);
            CP_COMMIT();
        }

        const uint32_t aTile = sbase + (uint32_t)((stg * TBUFH) * 2);
        const uint32_t bTile = sbase + (uint32_t)((BOFFH + stg * TBUFH) * 2);
        #pragma unroll
        for (int ks = 0; ks < 2; ks++) {
            const int kk = ks * 16;
            uint32_t af[4][4], bf[8][2];
            #pragma unroll
            for (int i = 0; i < 4; i++) {
                const uint32_t addr = aTile +
                    (uint32_t)(((a_row + i * 16) * GSH + kk + a_col8) * 2);
                LDSM_X4(af[i][0], af[i][1], af[i][2], af[i][3], addr);
            }
            #pragma unroll
            for (int jp = 0; jp < 4; jp++) {
                const int cb = warpN + jp * 16;
                const uint32_t addr = bTile +
                    (uint32_t)(((cb + b_row) * GSH + kk + b_col8) * 2);
                LDSM_X4(bf[2 * jp][0], bf[2 * jp][1],
                        bf[2 * jp + 1][0], bf[2 * jp + 1][1], addr);
            }
            #pragma unroll
            for (int i = 0; i < 4; i++)
                #pragma unroll
                for (int j = 0; j < 8; j++)
                    MMA_F16(acc[i][j], af[i], bf[j]);
        }
        stg = (stg + 1 >= NSTG) ? 0 : stg + 1;
    }

    #pragma unroll
    for (int i = 0; i < 4; i++) {
        const int row0 = bm + warpM + i * 16 + lr;
        #pragma unroll
        for (int j = 0; j < 8; j++) {
            const int col = bn + warpN + j * 8 + (lc << 1);
            const float b0 = __ldg(&bias[col]);
            const float b1 = __ldg(&bias[col + 1]);
            float v0 = acc[i][j][0] + b0;
            float v1 = acc[i][j][1] + b1;
            float v2 = acc[i][j][2] + b0;
            float v3 = acc[i][j][3] + b1;
            if (gelu) {
                v0 = 0.5f * v0 * (1.0f + erff(v0 * 0.70710678118654752f));
                v1 = 0.5f * v1 * (1.0f + erff(v1 * 0.70710678118654752f));
                v2 = 0.5f * v2 * (1.0f + erff(v2 * 0.70710678118654752f));
                v3 = 0.5f * v3 * (1.0f + erff(v3 * 0.70710678118654752f));
            }
            if (residual) {
                v0 += residual[(size_t)row0 * Nc + col];
                v1 += residual[(size_t)row0 * Nc + col + 1];
                v2 += residual[(size_t)(row0 + 8) * Nc + col];
                v3 += residual[(size_t)(row0 + 8) * Nc + col + 1];
            }
            if (out_half) {
                __half* oh = (__half*)outp;
                *(uint32_t*)(oh + (size_t)row0 * Nc + col)       = h2u(__floats2half2_rn(v0, v1));
                *(uint32_t*)(oh + (size_t)(row0 + 8) * Nc + col) = h2u(__floats2half2_rn(v2, v3));
            } else {
                float* of = (float*)outp;
                *(float2*)(of + (size_t)row0 * Nc + col)       = make_float2(v0, v1);
                *(float2*)(of + (size_t)(row0 + 8) * Nc + col) = make_float2(v2, v3);
            }
        }
    }
}

// ---------------------------------------------------------------------------
// Vectorized RoPE (unchanged)
// ---------------------------------------------------------------------------
__global__ void __launch_bounds__(256) rope2_kernel(
    __half* __restrict__ qp, __half* __restrict__ kp,
    const float* __restrict__ cosb, const float* __restrict__ sinb)
{
    __half* t = blockIdx.z ? kp : qp;
    int idx = blockIdx.x * 256 + threadIdx.x;
    const int ci = idx & 3; idx >>= 2;
    const int h = idx & (Hh - 1); idx >>= 4;
    const int n = idx & (Nn_ - 1); idx >>= 11;
    const int b = idx;
    const int c = ci * 8;
    const size_t base = ((size_t)(b * Nn_ + n)) * Cdim + h * Dd;

    uint4 lo = *(uint4*)(t + base + c);
    uint4 hi = *(uint4*)(t + base + c + 32);
    const __half* xl = (const __half*)&lo;
    const __half* xh = (const __half*)&hi;

    const float* cb = cosb + n * Dd;
    const float* sb = sinb + n * Dd;
    float cl[8], sl[8], ch[8], sh[8];
    *(float4*)&cl[0] = *(const float4*)(cb + c);
    *(float4*)&cl[4] = *(const float4*)(cb + c + 4);
    *(float4*)&ch[0] = *(const float4*)(cb + c + 32);
    *(float4*)&ch[4] = *(const float4*)(cb + c + 36);
    *(float4*)&sl[0] = *(const float4*)(sb + c);
    *(float4*)&sl[4] = *(const float4*)(sb + c + 4);
    *(float4*)&sh[0] = *(const float4*)(sb + c + 32);
    *(float4*)&sh[4] = *(const float4*)(sb + c + 36);

    uint4 olo, ohi;
    __half* ol = (__half*)&olo;
    __half* oh = (__half*)&ohi;
    #pragma unroll
    for (int j = 0; j < 8; j++) {
        const float x1 = __half2float(xl[j]);
        const float x2 = __half2float(xh[j]);
        ol[j] = __float2half_rn(x1 * cl[j] - x2 * sl[j]);
        oh[j] = __float2half_rn(x2 * ch[j] + x1 * sh[j]);
    }
    *(uint4*)(t + base + c)      = olo;
    *(uint4*)(t + base + c + 32) = ohi;
}

// ---------------------------------------------------------------------------
// Flash attention (unchanged from R16): fp16 mma, ex2.f16x2, P in registers,
// 3-stage cp.async K/V pipeline, V row-major + ldmatrix.trans for PV.
// ---------------------------------------------------------------------------
#define QSH 72
#define KV_ST (64 * QSH)
#define F_QS 0
#define F_KV (128 * QSH)
#define FLASH_SMEM ((128 * QSH + 3 * 2 * KV_ST) * 2)

__global__ void __launch_bounds__(256) flash_kernel(
    const __half* __restrict__ q, const __half* __restrict__ k,
    const __half* __restrict__ v, __half* __restrict__ out)
{
    extern __shared__ __half smf[];
    __half* Qs = smf + F_QS;
    const uint32_t sfbase = (uint32_t)__cvta_generic_to_shared(smf);

    const int tid  = threadIdx.x;
    const int wid  = tid >> 5;
    const int lane = tid & 31;
    const int lr   = lane >> 2;
    const int lc   = lane & 3;
    const int rm   = wid * 16;

    const int b_row  = (lane & 7) + ((lane >> 4) & 1) * 8;
    const int b_col8 = ((lane >> 3) & 1) * 8;
    const int v_row  = (lane & 7) + ((lane >> 3) & 1) * 8;
    const int v_col8 = ((lane >> 4) & 1) * 8;

    const int bh = blockIdx.y;
    const int b = bh >> 4;
    const int h = bh & 15;
    const int q0 = blockIdx.x * 128;
    const float qscale = 0.125f * 1.4426950408889634f;

    const __half* kb0 = k + ((size_t)(b * Nn_)) * Cdim + h * Dd;
    const __half* vb0 = v + ((size_t)(b * Nn_)) * Cdim + h * Dd;

    #define LOAD_KV(stg, kv0)                                                 \
    do {                                                                      \
        const uint32_t kBase = sfbase + (uint32_t)((F_KV + (stg) * 2 * KV_ST) * 2); \
        const uint32_t vBase = kBase + (uint32_t)(KV_ST * 2);                 \
        _Pragma("unroll")                                                     \
        for (int i = 0; i < 2; i++) {                                         \
            const int id = tid + i * 256;                                     \
            const int r = id >> 3;                                            \
            const int c = (id & 7) * 8;                                       \
            CP_ASYNC16(kBase + (uint32_t)((r * QSH + c) * 2),                 \
                       kb0 + (size_t)((kv0) + r) * Cdim + c);                 \
            CP_ASYNC16(vBase + (uint32_t)((r * QSH + c) * 2),                 \
                       vb0 + (size_t)((kv0) + r) * Cdim + c);                 \
        }                                                                     \
    } while (0)

    LOAD_KV(0, 0);
    CP_COMMIT();
    LOAD_KV(1, 64);
    CP_COMMIT();

    const __half* qb = q + ((size_t)(b * Nn_ + q0)) * Cdim + h * Dd;
    #pragma unroll
    for (int i = 0; i < 4; i++) {
        const int idx = tid + i * 256;
        const int r = idx >> 3;
        const int c = (idx & 7) * 8;
        uint4 u = *(const uint4*)(qb + (size_t)r * Cdim + c);
        __half2* hp = (__half2*)&u;
        #pragma unroll
        for (int j = 0; j < 4; j++) {
            float2 f = __half22float2(hp[j]);
            hp[j] = __floats2half2_rn(f.x * qscale, f.y * qscale);
        }
        *(uint4*)&Qs[r * QSH + c] = u;
    }
    __syncthreads();

    uint32_t qf[4][4];
    #pragma unroll
    for (int ks = 0; ks < 4; ks++) {
        const int kk = ks * 16;
        qf[ks][0] = *(const uint32_t*)&Qs[(rm + lr) * QSH + kk + 2 * lc];
        qf[ks][1] = *(const uint32_t*)&Qs[(rm + lr + 8) * QSH + kk + 2 * lc];
        qf[ks][2] = *(const uint32_t*)&Qs[(rm + lr) * QSH + kk + 2 * lc + 8];
        qf[ks][3] = *(const uint32_t*)&Qs[(rm + lr + 8) * QSH + kk + 2 * lc + 8];
    }

    float m0 = -1e30f, m1 = -1e30f, l0 = 0.f, l1 = 0.f;
    float oacc[8][4];
    #pragma unroll
    for (int nt = 0; nt < 8; nt++)
        #pragma unroll
        for (int r = 0; r < 4; r++) oacc[nt][r] = 0.f;

    const int ntiles = Nn_ / 64;
    int stg = 0;
    for (int it = 0; it < ntiles; it++) {
        if (it + 1 < ntiles) { CP_WAIT(1); } else { CP_WAIT(0); }
        __syncthreads();

        if (it + 2 < ntiles) {
            const int ns = (stg + 2 >= 3) ? stg - 1 : stg + 2;
            LOAD_KV(ns, (it + 2) * 64);
            CP_COMMIT();
        }

        const uint32_t ksBase = sfbase + (uint32_t)((F_KV + stg * 2 * KV_ST) * 2);
        const uint32_t vsBase = ksBase + (uint32_t)(KV_ST * 2);

        float sacc[8][4];
        #pragma unroll
        for (int nt = 0; nt < 8; nt++)
            #pragma unroll
            for (int r = 0; r < 4; r++) sacc[nt][r] = 0.f;
        #pragma unroll
        for (int ks = 0; ks < 4; ks++) {
            const int kk = ks * 16;
            uint32_t bf[8][2];
            #pragma unroll
            for (int jp = 0; jp < 4; jp++) {
                const uint32_t addr = ksBase +
                    (uint32_t)(((jp * 16 + b_row) * QSH + kk + b_col8) * 2);
                LDSM_X4(bf[2 * jp][0], bf[2 * jp][1],
                        bf[2 * jp + 1][0], bf[2 * jp + 1][1], addr);
            }
            #pragma unroll
            for (int nt = 0; nt < 8; nt++)
                MMA_F16(sacc[nt], qf[ks], bf[nt]);
        }

        float mx0 = -1e30f, mx1 = -1e30f;
        #pragma unroll
        for (int nt = 0; nt < 8; nt++) {
            mx0 = fmaxf(mx0, fmaxf(sacc[nt][0], sacc[nt][1]));
            mx1 = fmaxf(mx1, fmaxf(sacc[nt][2], sacc[nt][3]));
        }
        #pragma unroll
        for (int o = 1; o < 4; o <<= 1) {
            mx0 = fmaxf(mx0, __shfl_xor_sync(0xffffffffu, mx0, o, 4));
            mx1 = fmaxf(mx1, __shfl_xor_sync(0xffffffffu, mx1, o, 4));
        }
        const float mn0 = fmaxf(m0, mx0);
        const float mn1 = fmaxf(m1, mx1);
        const float al0 = exp2f(m0 - mn0);
        const float al1 = exp2f(m1 - mn1);
        float rs0 = 0.f, rs1 = 0.f;
        uint32_t pf[4][4];
        #pragma unroll
        for (int ks = 0; ks < 4; ks++) {
            const int ntA = 2 * ks, ntB = 2 * ks + 1;
            __half2 d0 = __floats2half2_rn(sacc[ntA][0] - mn0, sacc[ntA][1] - mn0);
            __half2 d1 = __floats2half2_rn(sacc[ntA][2] - mn1, sacc[ntA][3] - mn1);
            __half2 d2 = __floats2half2_rn(sacc[ntB][0] - mn0, sacc[ntB][1] - mn0);
            __half2 d3 = __floats2half2_rn(sacc[ntB][2] - mn1, sacc[ntB][3] - mn1);
            EX2_F16X2(pf[ks][0], h2u(d0));
            EX2_F16X2(pf[ks][1], h2u(d1));
            EX2_F16X2(pf[ks][2], h2u(d2));
            EX2_F16X2(pf[ks][3], h2u(d3));
            const float2 f0 = __half22float2(*(__half2*)&pf[ks][0]);
            const float2 f1 = __half22float2(*(__half2*)&pf[ks][1]);
            const float2 f2 = __half22float2(*(__half2*)&pf[ks][2]);
            const float2 f3 = __half22float2(*(__half2*)&pf[ks][3]);
            rs0 += f0.x + f0.y + f2.x + f2.y;
            rs1 += f1.x + f1.y + f3.x + f3.y;
        }
        #pragma unroll
        for (int o = 1; o < 4; o <<= 1) {
            rs0 += __shfl_xor_sync(0xffffffffu, rs0, o, 4);
            rs1 += __shfl_xor_sync(0xffffffffu, rs1, o, 4);
        }
        l0 = l0 * al0 + rs0;  m0 = mn0;
        l1 = l1 * al1 + rs1;  m1 = mn1;
        #pragma unroll
        for (int nt = 0; nt < 8; nt++) {
            oacc[nt][0] *= al0; oacc[nt][1] *= al0;
            oacc[nt][2] *= al1; oacc[nt][3] *= al1;
        }

        #pragma unroll
        for (int ks = 0; ks < 4; ks++) {
            const int kk = ks * 16;
            uint32_t bf[8][2];
            #pragma unroll
            for (int jp = 0; jp < 4; jp++) {
                const uint32_t addr = vsBase +
                    (uint32_t)(((kk + v_row) * QSH + jp * 16 + v_col8) * 2);
                LDSM_X4_T(bf[2 * jp][0], bf[2 * jp][1],
                          bf[2 * jp + 1][0], bf[2 * jp + 1][1], addr);
            }
            #pragma unroll
            for (int nt = 0; nt < 8; nt++)
                MMA_F16(oacc[nt], pf[ks], bf[nt]);
        }

        stg = (stg + 1 >= 3) ? 0 : stg + 1;
    }

    const float il0 = 1.0f / l0;
    const float il1 = 1.0f / l1;
    __half* ob = out + ((size_t)(b * Nn_ + q0 + rm)) * Cdim + h * Dd;
    #pragma unroll
    for (int nt = 0; nt < 8; nt++) {
        const int col = nt * 8 + 2 * lc;
        *(uint32_t*)(ob + (size_t)lr * Cdim + col) =
            h2u(__floats2half2_rn(oacc[nt][0] * il0, oacc[nt][1] * il0));
        *(uint32_t*)(ob + (size_t)(lr + 8) * Cdim + col) =
            h2u(__floats2half2_rn(oacc[nt][2] * il1, oacc[nt][3] * il1));
    }
}

// ---------------------------------------------------------------------------
extern "C" void kernel_launch(void* const* d_in, const int* in_sizes, int n_in,
                              void* d_out, int out_size)
{
    const float* x    = (const float*)d_in[0];
    const float* rcos = (const float*)d_in[1];
    const float* rsin = (const float*)d_in[2];
    const float* g1   = (const float*)d_in[3];
    const float* be1  = (const float*)d_in[4];
    const float* Wq   = (const float*)d_in[5];
    const float* bq   = (const float*)d_in[6];
    const float* Wk   = (const float*)d_in[7];
    const float* bk   = (const float*)d_in[8];
    const float* Wv   = (const float*)d_in[9];
    const float* bv   = (const float*)d_in[10];
    const float* Wo   = (const float*)d_in[11];
    const float* bo   = (const float*)d_in[12];
    const float* g2   = (const float*)d_in[13];
    const float* be2  = (const float*)d_in[14];
    const float* W1   = (const float*)d_in[15];
    const float* b1   = (const float*)d_in[16];
    const float* W2   = (const float*)d_in[17];
    const float* b2   = (const float*)d_in[18];
    float* out = (float*)d_out;

    unsigned char* base = nullptr;
    cudaGetSymbolAddress((void**)&base, g_scratch);
    __half* p_h   = (__half*)(base + OFF_H);
    __half* p_q   = (__half*)(base + OFF_Q);
    __half* p_k   = (__half*)(base + OFF_K);
    __half* p_v   = (__half*)(base + OFF_V);
    __half* p_att = (__half*)(base + OFF_ATT);
    __half* p_mlp = (__half*)(base + OFF_MLP);
    float*  p_x2  = (float*)(base + OFF_X2);
    __half* p_wq  = (__half*)(base + OFF_WQ);
    __half* p_wk  = (__half*)(base + OFF_WK);
    __half* p_wv  = (__half*)(base + OFF_WV);
    __half* p_wo  = (__half*)(base + OFF_WO);
    __half* p_w1  = (__half*)(base + OFF_W1);
    __half* p_w2  = (__half*)(base + OFF_W2);

    cudaFuncSetAttribute(flash_kernel,
                         cudaFuncAttributeMaxDynamicSharedMemorySize, FLASH_SMEM);
    cudaFuncSetAttribute(hgemm_kernel,
                         cudaFuncAttributeMaxDynamicSharedMemorySize, GEMM_SMEM);

    // 0. weights -> fp16
    const int nC4 = (Cdim * Cdim) / 4;
    const int nF4 = (Cdim * Fdim) / 4;
    ConvSet cs;
    cs.in[0] = (const float4*)Wq; cs.out[0] = (__half2*)p_wq;
    cs.in[1] = (const float4*)Wk; cs.out[1] = (__half2*)p_wk;
    cs.in[2] = (const float4*)Wv; cs.out[2] = (__half2*)p_wv;
    cs.in[3] = (const float4*)Wo; cs.out[3] = (__half2*)p_wo;
    cs.in[4] = (const float4*)W1; cs.out[4] = (__half2*)p_w1;
    cs.in[5] = (const float4*)W2; cs.out[5] = (__half2*)p_w2;
    cs.start[0] = 0;
    cs.start[1] = nC4;
    cs.start[2] = 2 * nC4;
    cs.start[3] = 3 * nC4;
    cs.start[4] = 4 * nC4;
    cs.start[5] = 4 * nC4 + nF4;
    cs.start[6] = 4 * nC4 + 2 * nF4;
    conv_half_kernel<<<3072, 256>>>(cs);

    // 1. LN1 -> half
    ln_kernel<<<Mrows, 256>>>(x, g1, be1, p_h);

    // 2. fused QKV projections -> half
    GemmSet qkv;
    qkv.W[0] = p_wq; qkv.W[1] = p_wk; qkv.W[2] = p_wv;
    qkv.bias[0] = bq; qkv.bias[1] = bk; qkv.bias[2] = bv;
    qkv.out[0] = p_q; qkv.out[1] = p_k; qkv.out[2] = p_v;
    hgemm_kernel<<<dim3(Cdim / 128, Mrows / 128, 3), 128, GEMM_SMEM>>>(
        p_h, qkv, nullptr, Mrows, Cdim, Cdim, 0, 1);

    // 3. RoPE
    rope2_kernel<<<dim3((Bb * Nn_ * Hh * 4) / 256, 1, 2), 256>>>(p_q, p_k, rcos, rsin);

    // 4. attention -> half
    flash_kernel<<<dim3(Nn_ / 128, Bb * Hh), 256, FLASH_SMEM>>>(p_q, p_k, p_v, p_att);

    // 5. output projection + fp32 residual -> fp32 x2
    GemmSet so;
    so.W[0] = p_wo; so.bias[0] = bo; so.out[0] = p_x2;
    so.W[1] = so.W[2] = nullptr; so.bias[1] = so.bias[2] = nullptr;
    so.out[1] = so.out[2] = nullptr;
    hgemm_kernel<<<dim3(Cdim / 128, Mrows / 128, 1), 128, GEMM_SMEM>>>(
        p_att, so, x, Mrows, Cdim, Cdim, 0, 0);

    // 6. LN2 -> half
    ln_kernel<<<Mrows, 256>>>(p_x2, g2, be2, p_h);

    // 7. MLP up + GELU -> half
    GemmSet s1;
    s1.W[0] = p_w1; s1.bias[0] = b1; s1.out[0] = p_mlp;
    s1.W[1] = s1.W[2] = nullptr; s1.bias[1] = s1.bias[2] = nullptr;
    s1.out[1] = s1.out[2] = nullptr;
    hgemm_kernel<<<dim3(Fdim / 128, Mrows / 128, 1), 128, GEMM_SMEM>>>(
        p_h, s1, nullptr, Mrows, Fdim, Cdim, 1, 1);

    // 8. MLP down + fp32 residual -> fp32 output
    GemmSet s2;
    s2.W[0] = p_w2; s2.bias[0] = b2; s2.out[0] = out;
    s2.W[1] = s2.W[2] = nullptr; s2.bias[1] = s2.bias[2] = nullptr;
    s2.out[1] = s2.out[2] = nullptr;
    hgemm_kernel<<<dim3(Cdim / 128, Mrows / 128, 1), 128, GEMM_SMEM>>>(
        p_mlp, s2, p_x2, Mrows, Cdim, Fdim, 0, 0);
}